// round 3
// baseline (speedup 1.0000x reference)
#include <cuda_runtime.h>
#include <cstdint>

#define BATCH 64
#define SEQ   4096
#define LBL   128
#define KTG   4
#define IGNORE_INDEX (-100)

// Scratch (no device allocations allowed).
__device__ int    g_first_invalid[BATCH];
__device__ double g_acc[BATCH];

// Reset scratch every launch so the captured graph is replay-deterministic.
__global__ void init_kernel() {
    int i = threadIdx.x;
    if (i < BATCH) {
        g_first_invalid[i] = SEQ;
        g_acc[i] = 0.0;
    }
}

// Pass over target only (4 MB, int32): first invalid position per batch row.
__global__ void scan_invalid_kernel(const int* __restrict__ target) {
    int token = blockIdx.x * blockDim.x + threadIdx.x;
    if (token >= BATCH * SEQ) return;
    // one int4 = the 4 targets of this token
    const int4 t = reinterpret_cast<const int4*>(target)[token];
    if (t.x == IGNORE_INDEX || t.y == IGNORE_INDEX ||
        t.z == IGNORE_INDEX || t.w == IGNORE_INDEX)
        atomicMin(&g_first_invalid[token >> 12], token & (SEQ - 1));
}

// One warp per token. Lane i owns columns [4i, 4i+4).
__global__ __launch_bounds__(256) void loss_kernel(
    const float* __restrict__ emit,
    const int*   __restrict__ target)
{
    const int warp  = threadIdx.x >> 5;
    const int lane  = threadIdx.x & 31;
    const int token = blockIdx.x * 8 + warp;     // 8 warps/block
    const int b = token >> 12;                   // S = 4096
    const int s = token & (SEQ - 1);

    __shared__ float partial[8];

    float loss = 0.0f;
    if (s < g_first_invalid[b]) {
        // 512B coalesced row load: lane i -> float4 at column 4i
        const float4 v =
            reinterpret_cast<const float4*>(emit + (size_t)token * LBL)[lane];

        // warp max
        float m = fmaxf(fmaxf(v.x, v.y), fmaxf(v.z, v.w));
#pragma unroll
        for (int o = 16; o; o >>= 1)
            m = fmaxf(m, __shfl_xor_sync(0xffffffffu, m, o));

        const float ex = __expf(v.x - m);
        const float ey = __expf(v.y - m);
        const float ez = __expf(v.z - m);
        const float ew = __expf(v.w - m);
        float se = (ex + ey) + (ez + ew);   // partial sum_all

        // sum_true: owning lane contributes its exp value per target index.
        float st = 0.0f;
        const int4 t = reinterpret_cast<const int4*>(target)[token];
        const int tk[KTG] = {t.x, t.y, t.z, t.w};
#pragma unroll
        for (int k = 0; k < KTG; k++) {
            const int idx = tk[k];
            if ((idx >> 2) == lane) {
                const int c = idx & 3;
                st += (c == 0 ? ex : c == 1 ? ey : c == 2 ? ez : ew);
            }
        }

        // fused warp reductions
#pragma unroll
        for (int o = 16; o; o >>= 1) {
            se += __shfl_xor_sync(0xffffffffu, se, o);
            st += __shfl_xor_sync(0xffffffffu, st, o);
        }

        loss = __logf(se) - __logf(st);      // m cancels exactly
    }

    if (lane == 0) partial[warp] = loss;
    __syncthreads();

    if (threadIdx.x == 0) {
        float bs = 0.0f;
#pragma unroll
        for (int w = 0; w < 8; w++) bs += partial[w];
        // all 8 tokens in this block share the same b (4096 % 8 == 0)
        atomicAdd(&g_acc[b], (double)bs);
    }
}

__global__ void final_kernel(float* __restrict__ out) {
    if (threadIdx.x == 0 && blockIdx.x == 0) {
        double sum = 0.0;
#pragma unroll
        for (int i = 0; i < BATCH; i++) sum += g_acc[i];
        out[0] = (float)sum;
    }
}

extern "C" void kernel_launch(void* const* d_in, const int* in_sizes, int n_in,
                              void* d_out, int out_size)
{
    const float* emit   = (const float*)d_in[0];
    const int*   target = (const int*)d_in[1];
    float*       out    = (float*)d_out;

    init_kernel<<<1, BATCH>>>();

    const int ntok = BATCH * SEQ;
    scan_invalid_kernel<<<(ntok + 255) / 256, 256>>>(target);

    // one warp per token, 8 warps per block
    loss_kernel<<<ntok / 8, 256>>>(emit, target);

    final_kernel<<<1, 32>>>(out);
}

// round 4
// speedup vs baseline: 1.8053x; 1.8053x over previous
#include <cuda_runtime.h>
#include <cstdint>

#define BATCH 64
#define SEQ   4096
#define LBL   128
#define IGN   (-100)

__device__ int    g_first_invalid[BATCH];
__device__ double g_acc[BATCH];          // zero-initialized; self-resetting

// One block per batch row: compute first invalid position, no atomics, no init.
__global__ __launch_bounds__(512) void scan_kernel(const int* __restrict__ target) {
    __shared__ int red[512];
    const int b = blockIdx.x;
    int m = SEQ;
#pragma unroll
    for (int i = 0; i < 8; i++) {
        const int s = i * 512 + threadIdx.x;
        const int4 t = reinterpret_cast<const int4*>(target)[b * SEQ + s];
        if (t.x == IGN || t.y == IGN || t.z == IGN || t.w == IGN) m = min(m, s);
    }
    red[threadIdx.x] = m;
    __syncthreads();
#pragma unroll
    for (int off = 256; off; off >>= 1) {
        if (threadIdx.x < off)
            red[threadIdx.x] = min(red[threadIdx.x], red[threadIdx.x + off]);
        __syncthreads();
    }
    if (threadIdx.x == 0) g_first_invalid[b] = red[0];
}

// 4 tokens per warp, 8 lanes per token, 4 x float4 per lane (MLP=4).
__global__ __launch_bounds__(256) void loss_kernel(
    const float* __restrict__ emit,
    const int*   __restrict__ target)
{
    const int warp  = threadIdx.x >> 5;
    const int lane  = threadIdx.x & 31;
    const int tg    = lane >> 3;         // token-in-warp 0..3
    const int g     = lane & 7;          // lane-in-group 0..7
    const int token = blockIdx.x * 32 + warp * 4 + tg;
    const int b     = token >> 12;       // SEQ = 4096
    const int s     = token & (SEQ - 1);

    // Batched independent loads: 4 x 16B per lane + targets.
    const float4* row = reinterpret_cast<const float4*>(emit + (size_t)token * LBL);
    const float4 v0 = row[g];
    const float4 v1 = row[8 + g];
    const float4 v2 = row[16 + g];
    const float4 v3 = row[24 + g];
    const int4   t  = reinterpret_cast<const int4*>(target)[token];

    float se = 0.0f, st = 0.0f;

    // idx>>2 == 8*pass + g identifies the owning (pass, lane); idx&3 the element.
#define PASS(P, V)                                                              \
    {                                                                           \
        const float e0 = __expf(V.x), e1 = __expf(V.y),                         \
                    e2 = __expf(V.z), e3 = __expf(V.w);                         \
        se += (e0 + e1) + (e2 + e3);                                            \
        const int base = (P) * 8 + g;                                           \
        if ((t.x >> 2) == base)                                                 \
            st += ((t.x & 3) == 0 ? e0 : (t.x & 3) == 1 ? e1 : (t.x & 3) == 2 ? e2 : e3); \
        if ((t.y >> 2) == base)                                                 \
            st += ((t.y & 3) == 0 ? e0 : (t.y & 3) == 1 ? e1 : (t.y & 3) == 2 ? e2 : e3); \
        if ((t.z >> 2) == base)                                                 \
            st += ((t.z & 3) == 0 ? e0 : (t.z & 3) == 1 ? e1 : (t.z & 3) == 2 ? e2 : e3); \
        if ((t.w >> 2) == base)                                                 \
            st += ((t.w & 3) == 0 ? e0 : (t.w & 3) == 1 ? e1 : (t.w & 3) == 2 ? e2 : e3); \
    }
    PASS(0, v0) PASS(1, v1) PASS(2, v2) PASS(3, v3)
#undef PASS

    // Reduce within the 8-lane group (offsets 1,2,4 stay inside the group).
#pragma unroll
    for (int o = 1; o <= 4; o <<= 1) {
        se += __shfl_xor_sync(0xffffffffu, se, o);
        st += __shfl_xor_sync(0xffffffffu, st, o);
    }

    const int fi = g_first_invalid[b];
    const float loss = (s < fi) ? (__logf(se) - __logf(st)) : 0.0f;

    __shared__ float part[32];
    if (g == 0) part[warp * 4 + tg] = loss;
    __syncthreads();

    if (threadIdx.x < 32) {
        float x = part[threadIdx.x];
#pragma unroll
        for (int o = 16; o; o >>= 1) x += __shfl_xor_sync(0xffffffffu, x, o);
        if (threadIdx.x == 0)
            atomicAdd(&g_acc[b], (double)x);   // all 32 tokens share b
    }
}

// Parallel reduce of 64 doubles + self-reset for next replay.
__global__ void final_kernel(float* __restrict__ out) {
    const int i = threadIdx.x;               // 64 threads
    __shared__ double wsum[2];
    double x = g_acc[i];
    g_acc[i] = 0.0;                          // restore state for next launch
#pragma unroll
    for (int o = 16; o; o >>= 1) x += __shfl_xor_sync(0xffffffffu, x, o);
    if ((i & 31) == 0) wsum[i >> 5] = x;
    __syncthreads();
    if (i == 0) out[0] = (float)(wsum[0] + wsum[1]);
}

extern "C" void kernel_launch(void* const* d_in, const int* in_sizes, int n_in,
                              void* d_out, int out_size)
{
    const float* emit   = (const float*)d_in[0];
    const int*   target = (const int*)d_in[1];
    float*       out    = (float*)d_out;

    scan_kernel<<<BATCH, 512>>>(target);
    loss_kernel<<<(BATCH * SEQ) / 32, 256>>>(emit, target);
    final_kernel<<<1, 64>>>(out);
}